// round 13
// baseline (speedup 1.0000x reference)
#include <cuda_runtime.h>
#include <cuda_bf16.h>
#include <math.h>

// ---------------------------------------------------------------------------
// Problem constants
// ---------------------------------------------------------------------------
#define BATCH   16
#define SEQ     577
#define TOK     (BATCH * SEQ)        // 9232
#define DIM     1024
#define HEADS   16
#define HDIM    64
#define HIDDEN  4096
#define EPS     1e-5f
#define SCALE   0.125f
#define SCL2    0.18033688011112042f   // SCALE * log2(e)

// ---------------------------------------------------------------------------
// Scratch
// ---------------------------------------------------------------------------
__device__ float g_xn [TOK * DIM];
__device__ float g_qkv[TOK * 3 * DIM];
__device__ float g_y  [TOK * DIM];
__device__ float g_x1 [TOK * DIM];
__device__ float g_h  [TOK * HIDDEN];
__device__ float g_wq [3 * DIM * DIM];
__device__ float g_wp [DIM * DIM];
__device__ float g_w1 [HIDDEN * DIM];
__device__ float g_w2 [DIM * HIDDEN];

// ---------------------------------------------------------------------------
// Common helpers
// ---------------------------------------------------------------------------
__device__ __forceinline__ unsigned f2tf32(float f) {
    unsigned u;
    asm("cvt.rna.tf32.f32 %0, %1;" : "=r"(u) : "f"(f));
    return u;
}
__device__ __forceinline__ float tf32r(float f) {
    return __uint_as_float(f2tf32(f));
}
// K-REMAP CONVENTION: within each mma k8-step, fragment slot t (t=0..3)
// carries global k = kk + 2t, slot t+4 carries k = kk + 2t + 1. Valid since
// mma reduces over all 8 slots; both A and B fragments use the same map.
__device__ __forceinline__ void mma_tf32(
    float c[4], unsigned a0, unsigned a1, unsigned a2, unsigned a3,
    unsigned b0, unsigned b1)
{
    asm volatile(
        "mma.sync.aligned.m16n8k8.row.col.f32.tf32.tf32.f32 "
        "{%0,%1,%2,%3}, {%4,%5,%6,%7}, {%8,%9}, {%0,%1,%2,%3};\n"
        : "+f"(c[0]), "+f"(c[1]), "+f"(c[2]), "+f"(c[3])
        : "r"(a0), "r"(a1), "r"(a2), "r"(a3), "r"(b0), "r"(b1));
}
__device__ __forceinline__ void cp_async16(void* smem_dst, const void* gsrc) {
    unsigned s = (unsigned)__cvta_generic_to_shared(smem_dst);
    asm volatile("cp.async.cg.shared.global [%0], [%1], 16;\n" :: "r"(s), "l"(gsrc));
}
__device__ __forceinline__ void cp_commit() {
    asm volatile("cp.async.commit_group;\n");
}
template<int N>
__device__ __forceinline__ void cp_wait() {
    asm volatile("cp.async.wait_group %0;\n" :: "n"(N));
}

// Fast 2^x on the FMA/ALU pipes (no MUFU).
__device__ __forceinline__ float exp2_fast(float x) {
    float xc = fmaxf(x, -126.f);
    float fi = floorf(xc);
    float f = xc - fi;
    float p = 1.5403530e-4f;
    p = fmaf(p, f, 1.3333558e-3f);
    p = fmaf(p, f, 9.6181291e-3f);
    p = fmaf(p, f, 5.5504109e-2f);
    p = fmaf(p, f, 2.4022651e-1f);
    p = fmaf(p, f, 6.9314718e-1f);
    p = fmaf(p, f, 1.0f);
    int i = (int)fi;
    return __int_as_float((i + 127) << 23) * p;
}

// ---------------------------------------------------------------------------
// tf32 pre-round kernel (weights)
// ---------------------------------------------------------------------------
__global__ __launch_bounds__(256) void tf32_round_kernel(
    const float* __restrict__ in, float* __restrict__ out, int n4)
{
    int i = blockIdx.x * 256 + threadIdx.x;
    if (i < n4) {
        float4 v = ((const float4*)in)[i];
        float4 o;
        o.x = tf32r(v.x); o.y = tf32r(v.y); o.z = tf32r(v.z); o.w = tf32r(v.w);
        ((float4*)out)[i] = o;
    }
}

// ---------------------------------------------------------------------------
// LayerNorm (output tf32-rounded)
// ---------------------------------------------------------------------------
__device__ __forceinline__ float block_reduce_sum(float v, float* red) {
    int lane = threadIdx.x & 31, wid = threadIdx.x >> 5;
    #pragma unroll
    for (int o = 16; o > 0; o >>= 1) v += __shfl_xor_sync(0xffffffffu, v, o);
    if (lane == 0) red[wid] = v;
    __syncthreads();
    v = (lane < 8) ? red[lane] : 0.f;
    #pragma unroll
    for (int o = 4; o > 0; o >>= 1) v += __shfl_xor_sync(0xffffffffu, v, o);
    v = __shfl_sync(0xffffffffu, v, 0);
    return v;
}

__global__ __launch_bounds__(256) void ln_kernel(
    const float* __restrict__ x, const float* __restrict__ g,
    const float* __restrict__ b, float* __restrict__ out)
{
    __shared__ float red[8];
    size_t row = blockIdx.x;
    const float4* xr = (const float4*)(x + row * DIM);
    int t = threadIdx.x;
    float4 v = xr[t];
    float s = v.x + v.y + v.z + v.w;
    float mean = block_reduce_sum(s, red) * (1.f / DIM);
    __syncthreads();
    float dx0 = v.x - mean, dx1 = v.y - mean, dx2 = v.z - mean, dx3 = v.w - mean;
    float s2 = dx0*dx0 + dx1*dx1 + dx2*dx2 + dx3*dx3;
    float var = block_reduce_sum(s2, red) * (1.f / DIM);
    float rs = rsqrtf(var + EPS);
    float4 gg = ((const float4*)g)[t];
    float4 bb = ((const float4*)b)[t];
    float4 o;
    o.x = tf32r(dx0 * rs * gg.x + bb.x);
    o.y = tf32r(dx1 * rs * gg.y + bb.y);
    o.z = tf32r(dx2 * rs * gg.z + bb.z);
    o.w = tf32r(dx3 * rs * gg.w + bb.w);
    ((float4*)(out + row * DIM))[t] = o;
}

// ---------------------------------------------------------------------------
// TF32 GEMM-NT v7: 256x128x32 CTA, 512 threads, 3-stage cp.async ring,
// ONE __syncthreads per k-tile (prefetch issued post-barrier => the ring
// reuse (t+2)%3 == (t-1)%3 is safe). v2 fragment loads via k-remap.
// RST=40: LDS.64 pair-bank coeff 20 mod 16 = 4 -> conflict-free.
// ---------------------------------------------------------------------------
#define EPI_BIAS 1
#define EPI_GELU 2
#define EPI_RES  4
#define EPI_T32O 8

#define GBM 256
#define GBN 128
#define GBK 32
#define RST 40
#define A_FLOATS (GBM * RST)                  // 10240
#define B_FLOATS (GBN * RST)                  // 5120
#define STG_FLOATS (A_FLOATS + B_FLOATS)      // 15360
#define GEMM_SMEM (3 * STG_FLOATS * (int)sizeof(float))   // 184320

template<int FLAGS>
__global__ __launch_bounds__(512, 1) void gemm_tf32(
    const float* __restrict__ A, const float* __restrict__ Bw,
    const float* __restrict__ bias, const float* __restrict__ res,
    float* __restrict__ C, int M, int Nc, int K)
{
    extern __shared__ float sm[];

    int tid = threadIdx.x;
    int m0 = blockIdx.y * GBM, n0 = blockIdx.x * GBN;

    int warp = tid >> 5, lane = tid & 31;
    int wm = warp & 3, wn = warp >> 2;      // 4 m x 4 n warp grid
    int mb = wm * 64, nb = wn * 32;
    int g  = lane >> 2;
    int tg = lane & 3;

    // loader coords: thread -> (row, 64B half)
    int l_row  = tid >> 1;                  // 0..255
    int l_half = (tid & 1) << 4;            // float offset 0 or 16

    float acc[4][4][4];
    #pragma unroll
    for (int i = 0; i < 4; i++)
        #pragma unroll
        for (int j = 0; j < 4; j++)
            #pragma unroll
            for (int c = 0; c < 4; c++) acc[i][j][c] = 0.f;

    const int T = K / GBK;

    int arr = m0 + l_row;
    int arow = arr < M ? arr : M - 1;
    const float* Ap = A + (size_t)arow * K;
    const float* Bp = (tid < 256) ? (Bw + (size_t)(n0 + (tid >> 1)) * K) : nullptr;

    // stage loader
    auto load_stage = [&](int s, int k0) {
        float* As = sm + s * STG_FLOATS;
        float* Bs = As + A_FLOATS;
        #pragma unroll
        for (int c = 0; c < 4; c++)
            cp_async16(&As[l_row * RST + l_half + 4 * c], Ap + k0 + l_half + 4 * c);
        if (tid < 256) {
            int brow = tid >> 1;
            #pragma unroll
            for (int c = 0; c < 4; c++)
                cp_async16(&Bs[brow * RST + l_half + 4 * c], Bp + k0 + l_half + 4 * c);
        }
    };

    // prologue: stages 0 and 1
    load_stage(0, 0);
    cp_commit();
    if (T > 1) { load_stage(1, GBK); }
    cp_commit();

    for (int t = 0; t < T; t++) {
        if (t + 2 < T) cp_wait<1>(); else cp_wait<0>();
        __syncthreads();
        // prefetch t+2 AFTER the barrier: every warp has finished reading the
        // buffer (t+2)%3 == (t-1)%3 at this point.
        if (t + 2 < T) {
            load_stage((t + 2) % 3, (t + 2) * GBK);
            cp_commit();
        }

        const float* stage = sm + (t % 3) * STG_FLOATS;
        const unsigned* as = (const unsigned*)stage;
        const unsigned* bs = (const unsigned*)(stage + A_FLOATS);
        #pragma unroll
        for (int ks = 0; ks < 4; ks++) {
            int kk = ks * 8;
            unsigned a[4][4];
            #pragma unroll
            for (int i = 0; i < 4; i++) {
                int r0 = (mb + i * 16 + g) * RST + kk + 2 * tg;
                uint2 lo = *(const uint2*)(as + r0);
                uint2 hi = *(const uint2*)(as + r0 + 8 * RST);
                a[i][0] = lo.x; a[i][2] = lo.y;
                a[i][1] = hi.x; a[i][3] = hi.y;
            }
            #pragma unroll
            for (int j = 0; j < 4; j++) {
                int c0 = (nb + j * 8 + g) * RST + kk + 2 * tg;
                uint2 bb = *(const uint2*)(bs + c0);
                #pragma unroll
                for (int i = 0; i < 4; i++)
                    mma_tf32(acc[i][j], a[i][0], a[i][1], a[i][2], a[i][3], bb.x, bb.y);
            }
        }
    }

    __syncthreads();   // protect nothing downstream; cheap, keeps epilogue clean

    #pragma unroll
    for (int i = 0; i < 4; i++) {
        #pragma unroll
        for (int j = 0; j < 4; j++) {
            int row0 = m0 + mb + i * 16 + g;
            int col  = n0 + nb + j * 8 + tg * 2;
            float bia0 = 0.f, bia1 = 0.f;
            if (FLAGS & EPI_BIAS) { bia0 = bias[col]; bia1 = bias[col + 1]; }
            #pragma unroll
            for (int half = 0; half < 2; half++) {
                int r = row0 + half * 8;
                if (r < M) {
                    float v0 = acc[i][j][half * 2 + 0] + bia0;
                    float v1 = acc[i][j][half * 2 + 1] + bia1;
                    if (FLAGS & EPI_GELU) {
                        v0 = 0.5f * v0 * (1.f + erff(v0 * 0.70710678118654752f));
                        v1 = 0.5f * v1 * (1.f + erff(v1 * 0.70710678118654752f));
                    }
                    size_t base = (size_t)r * Nc + col;
                    if (FLAGS & EPI_RES) {
                        float2 rr = *(const float2*)(res + base);
                        v0 += rr.x; v1 += rr.y;
                    }
                    if (FLAGS & EPI_T32O) { v0 = tf32r(v0); v1 = tf32r(v1); }
                    float2 o; o.x = v0; o.y = v1;
                    *(float2*)(C + base) = o;
                }
            }
        }
    }
}

// ---------------------------------------------------------------------------
// Attention v6 (unchanged from R12): register flash, k-remap, no shuffles.
// ---------------------------------------------------------------------------
#define FQ4   128
#define FC4   64
#define NCH4  10
#define QST4  72
#define KST4  72
#define VST4  68
#define A4_Q  0
#define A4_K  (A4_Q + FQ4 * QST4)               // 9216
#define A4_V  (A4_K + 2 * FC4 * KST4)           // 18432
#define ATT4_SMEM ((A4_V + 2 * FC4 * VST4) * (int)sizeof(float))  // 108544

__global__ __launch_bounds__(256, 2) void attn6_kernel(
    const float* __restrict__ qkv, float* __restrict__ out)
{
    extern __shared__ float sm[];
    float* qs = sm + A4_Q;
    float* kb = sm + A4_K;
    float* vb = sm + A4_V;

    int bh = blockIdx.y;
    int b = bh >> 4, h = bh & 15;
    int q0 = blockIdx.x * FQ4;
    int t = threadIdx.x;
    int warp = t >> 5, lane = t & 31;
    int g = lane >> 2, tg = lane & 3;
    int mb = warp * 16;

    const float* kq = qkv + (size_t)b * SEQ * (3 * DIM) + DIM + h * HDIM;
    const float* vq = qkv + (size_t)b * SEQ * (3 * DIM) + 2 * DIM + h * HDIM;

    for (int idx = t; idx < FQ4 * 16; idx += 256) {
        int r = idx >> 4, c4 = (idx & 15) << 2;
        int qr = q0 + r; if (qr >= SEQ) qr = SEQ - 1;
        float4 v = *(const float4*)(qkv + (size_t)(b * SEQ + qr) * (3 * DIM) + h * HDIM + c4);
        *(float4*)(qs + r * QST4 + c4) = v;
    }

    float m0 = -1e30f, m1 = -1e30f, l0 = 0.f, l1 = 0.f;
    float oacc[8][4];
    #pragma unroll
    for (int j = 0; j < 8; j++)
        #pragma unroll
        for (int c = 0; c < 4; c++) oacc[j][c] = 0.f;

    for (int idx = t; idx < FC4 * 16; idx += 256) {
        int r = idx >> 4, c4 = (idx & 15) << 2;
        int kr = r; if (kr >= SEQ) kr = SEQ - 1;
        cp_async16(&kb[r * KST4 + c4], kq + (size_t)kr * (3 * DIM) + c4);
        cp_async16(&vb[r * VST4 + c4], vq + (size_t)kr * (3 * DIM) + c4);
    }
    cp_commit();

    for (int c = 0; c < NCH4; c++) {
        int buf = c & 1;
        const float* kbuf = kb + buf * FC4 * KST4;
        const float* vbuf = vb + buf * FC4 * VST4;
        if (c + 1 < NCH4) {
            float* kn = kb + (buf ^ 1) * FC4 * KST4;
            float* vn = vb + (buf ^ 1) * FC4 * VST4;
            for (int idx = t; idx < FC4 * 16; idx += 256) {
                int r = idx >> 4, c4 = (idx & 15) << 2;
                int kr = (c + 1) * FC4 + r; if (kr >= SEQ) kr = SEQ - 1;
                cp_async16(&kn[r * KST4 + c4], kq + (size_t)kr * (3 * DIM) + c4);
                cp_async16(&vn[r * VST4 + c4], vq + (size_t)kr * (3 * DIM) + c4);
            }
            cp_commit();
            cp_wait<1>();
        } else {
            cp_wait<0>();
        }
        __syncthreads();

        // ---- S = Q @ K^T (v2 frag loads, k-remap) ----
        float p[8][4];
        #pragma unroll
        for (int j = 0; j < 8; j++)
            #pragma unroll
            for (int e = 0; e < 4; e++) p[j][e] = 0.f;

        const unsigned* ku = (const unsigned*)kbuf;
        const unsigned* qu = (const unsigned*)qs;
        #pragma unroll
        for (int k8 = 0; k8 < 8; k8++) {
            int kk = k8 * 8;
            int q0i = (mb + g) * QST4 + kk + 2 * tg;
            uint2 qa = *(const uint2*)(qu + q0i);
            uint2 qb = *(const uint2*)(qu + q0i + 8 * QST4);
            unsigned a0 = qa.x, a2 = qa.y, a1 = qb.x, a3 = qb.y;
            #pragma unroll
            for (int j = 0; j < 8; j++) {
                uint2 kv = *(const uint2*)(ku + (8 * j + g) * KST4 + kk + 2 * tg);
                mma_tf32(p[j], a0, a1, a2, a3, kv.x, kv.y);
            }
        }

        #pragma unroll
        for (int j = 0; j < 8; j++) {
            int gcol = c * FC4 + 8 * j + 2 * tg;
            bool ok0 = (gcol < SEQ), ok1 = (gcol + 1 < SEQ);
            p[j][0] = ok0 ? p[j][0] * SCL2 : -1e30f;
            p[j][1] = ok1 ? p[j][1] * SCL2 : -1e30f;
            p[j][2] = ok0 ? p[j][2] * SCL2 : -1e30f;
            p[j][3] = ok1 ? p[j][3] * SCL2 : -1e30f;
        }

        float cm0 = -1e30f, cm1 = -1e30f;
        #pragma unroll
        for (int j = 0; j < 8; j++) {
            cm0 = fmaxf(cm0, fmaxf(p[j][0], p[j][1]));
            cm1 = fmaxf(cm1, fmaxf(p[j][2], p[j][3]));
        }
        cm0 = fmaxf(cm0, __shfl_xor_sync(0xffffffffu, cm0, 1, 4));
        cm0 = fmaxf(cm0, __shfl_xor_sync(0xffffffffu, cm0, 2, 4));
        cm1 = fmaxf(cm1, __shfl_xor_sync(0xffffffffu, cm1, 1, 4));
        cm1 = fmaxf(cm1, __shfl_xor_sync(0xffffffffu, cm1, 2, 4));

        float mn0 = fmaxf(m0, cm0), mn1 = fmaxf(m1, cm1);
        float al0 = exp2_fast(m0 - mn0), al1 = exp2_fast(m1 - mn1);
        float s0 = 0.f, s1 = 0.f;
        #pragma unroll
        for (int j = 0; j < 8; j++) {
            p[j][0] = exp2_fast(p[j][0] - mn0); s0 += p[j][0];
            p[j][1] = exp2_fast(p[j][1] - mn0); s0 += p[j][1];
            p[j][2] = exp2_fast(p[j][2] - mn1); s1 += p[j][2];
            p[j][3] = exp2_fast(p[j][3] - mn1); s1 += p[j][3];
        }
        s0 += __shfl_xor_sync(0xffffffffu, s0, 1, 4);
        s0 += __shfl_xor_sync(0xffffffffu, s0, 2, 4);
        s1 += __shfl_xor_sync(0xffffffffu, s1, 1, 4);
        s1 += __shfl_xor_sync(0xffffffffu, s1, 2, 4);
        l0 = l0 * al0 + s0;  m0 = mn0;
        l1 = l1 * al1 + s1;  m1 = mn1;

        #pragma unroll
        for (int j = 0; j < 8; j++) {
            oacc[j][0] *= al0; oacc[j][1] *= al0;
            oacc[j][2] *= al1; oacc[j][3] *= al1;
        }

        // ---- O += P @ V : k-remap makes S-output fragment == A-fragment.
        const unsigned* vu = (const unsigned*)vbuf;
        #pragma unroll
        for (int jj = 0; jj < 8; jj++) {
            unsigned A0 = f2tf32(p[jj][0]);
            unsigned A1 = f2tf32(p[jj][2]);
            unsigned A2 = f2tf32(p[jj][1]);
            unsigned A3 = f2tf32(p[jj][3]);
            int vr0 = (8 * jj + 2 * tg) * VST4;
            int vr1 = vr0 + VST4;
            #pragma unroll
            for (int j2 = 0; j2 < 8; j2++) {
                unsigned b0 = vu[vr0 + 8 * j2 + g];
                unsigned b1 = vu[vr1 + 8 * j2 + g];
                mma_tf32(oacc[j2], A0, A1, A2, A3, b0, b1);
            }
        }
        __syncthreads();
    }

    {
        float li0 = 1.f / l0, li1 = 1.f / l1;
        #pragma unroll
        for (int j2 = 0; j2 < 8; j2++) {
            int col = h * HDIM + 8 * j2 + 2 * tg;
            int r0 = q0 + mb + g, r1 = r0 + 8;
            if (r0 < SEQ) {
                float2 o; o.x = tf32r(oacc[j2][0] * li0); o.y = tf32r(oacc[j2][1] * li0);
                *(float2*)(out + (size_t)(b * SEQ + r0) * DIM + col) = o;
            }
            if (r1 < SEQ) {
                float2 o; o.x = tf32r(oacc[j2][2] * li1); o.y = tf32r(oacc[j2][3] * li1);
                *(float2*)(out + (size_t)(b * SEQ + r1) * DIM + col) = o;
            }
        }
    }
}

// ---------------------------------------------------------------------------
// Launch
// ---------------------------------------------------------------------------
extern "C" void kernel_launch(void* const* d_in, const int* in_sizes, int n_in,
                              void* d_out, int out_size)
{
    const float* x      = (const float*)d_in[0];
    const float* w_qkv  = (const float*)d_in[1];
    const float* b_qkv  = (const float*)d_in[2];
    const float* w_proj = (const float*)d_in[3];
    const float* b_proj = (const float*)d_in[4];
    const float* ln1_g  = (const float*)d_in[5];
    const float* ln1_b  = (const float*)d_in[6];
    const float* ln2_g  = (const float*)d_in[7];
    const float* ln2_b  = (const float*)d_in[8];
    const float* w_fc1  = (const float*)d_in[9];
    const float* b_fc1  = (const float*)d_in[10];
    const float* w_fc2  = (const float*)d_in[11];
    const float* b_fc2  = (const float*)d_in[12];
    float* out = (float*)d_out;

    float *p_xn, *p_qkv, *p_y, *p_x1, *p_h, *p_wq, *p_wp, *p_w1, *p_w2;
    cudaGetSymbolAddress((void**)&p_xn,  g_xn);
    cudaGetSymbolAddress((void**)&p_qkv, g_qkv);
    cudaGetSymbolAddress((void**)&p_y,   g_y);
    cudaGetSymbolAddress((void**)&p_x1,  g_x1);
    cudaGetSymbolAddress((void**)&p_h,   g_h);
    cudaGetSymbolAddress((void**)&p_wq,  g_wq);
    cudaGetSymbolAddress((void**)&p_wp,  g_wp);
    cudaGetSymbolAddress((void**)&p_w1,  g_w1);
    cudaGetSymbolAddress((void**)&p_w2,  g_w2);

    cudaFuncSetAttribute(attn6_kernel,
        cudaFuncAttributeMaxDynamicSharedMemorySize, ATT4_SMEM);
    cudaFuncSetAttribute(gemm_tf32<EPI_BIAS | EPI_T32O>,
        cudaFuncAttributeMaxDynamicSharedMemorySize, GEMM_SMEM);
    cudaFuncSetAttribute(gemm_tf32<EPI_BIAS | EPI_RES>,
        cudaFuncAttributeMaxDynamicSharedMemorySize, GEMM_SMEM);
    cudaFuncSetAttribute(gemm_tf32<EPI_BIAS | EPI_GELU | EPI_T32O>,
        cudaFuncAttributeMaxDynamicSharedMemorySize, GEMM_SMEM);

    const int MB = (TOK + GBM - 1) / GBM;   // 37

    tf32_round_kernel<<<(3 * DIM * DIM / 4 + 255) / 256, 256>>>(w_qkv, p_wq, 3 * DIM * DIM / 4);
    tf32_round_kernel<<<(DIM * DIM / 4 + 255) / 256, 256>>>(w_proj, p_wp, DIM * DIM / 4);
    tf32_round_kernel<<<(HIDDEN * DIM / 4 + 255) / 256, 256>>>(w_fc1, p_w1, HIDDEN * DIM / 4);
    tf32_round_kernel<<<(DIM * HIDDEN / 4 + 255) / 256, 256>>>(w_fc2, p_w2, DIM * HIDDEN / 4);

    ln_kernel<<<TOK, 256>>>(x, ln1_g, ln1_b, p_xn);
    gemm_tf32<EPI_BIAS | EPI_T32O><<<dim3(3 * DIM / GBN, MB), 512, GEMM_SMEM>>>(
        p_xn, p_wq, b_qkv, nullptr, p_qkv, TOK, 3 * DIM, DIM);
    attn6_kernel<<<dim3((SEQ + FQ4 - 1) / FQ4, BATCH * HEADS), 256, ATT4_SMEM>>>(
        p_qkv, p_y);
    gemm_tf32<EPI_BIAS | EPI_RES><<<dim3(DIM / GBN, MB), 512, GEMM_SMEM>>>(
        p_y, p_wp, b_proj, x, p_x1, TOK, DIM, DIM);
    ln_kernel<<<TOK, 256>>>(p_x1, ln2_g, ln2_b, p_xn);
    gemm_tf32<EPI_BIAS | EPI_GELU | EPI_T32O><<<dim3(HIDDEN / GBN, MB), 512, GEMM_SMEM>>>(
        p_xn, p_w1, b_fc1, nullptr, p_h, TOK, HIDDEN, DIM);
    gemm_tf32<EPI_BIAS | EPI_RES><<<dim3(DIM / GBN, MB), 512, GEMM_SMEM>>>(
        p_h, p_w2, b_fc2, p_x1, out, TOK, DIM, HIDDEN);
}

// round 14
// speedup vs baseline: 1.4657x; 1.4657x over previous
#include <cuda_runtime.h>
#include <cuda_bf16.h>
#include <math.h>

// ---------------------------------------------------------------------------
// Problem constants
// ---------------------------------------------------------------------------
#define BATCH   16
#define SEQ     577
#define TOK     (BATCH * SEQ)        // 9232
#define DIM     1024
#define HEADS   16
#define HDIM    64
#define HIDDEN  4096
#define EPS     1e-5f
#define SCALE   0.125f
#define SCL2    0.18033688011112042f   // SCALE * log2(e)

// ---------------------------------------------------------------------------
// Scratch
// ---------------------------------------------------------------------------
__device__ float g_xn [TOK * DIM];
__device__ float g_qkv[TOK * 3 * DIM];
__device__ float g_y  [TOK * DIM];
__device__ float g_x1 [TOK * DIM];
__device__ float g_h  [TOK * HIDDEN];
__device__ float g_wq [3 * DIM * DIM];
__device__ float g_wp [DIM * DIM];
__device__ float g_w1 [HIDDEN * DIM];
__device__ float g_w2 [DIM * HIDDEN];

// ---------------------------------------------------------------------------
// Common helpers
// ---------------------------------------------------------------------------
__device__ __forceinline__ unsigned f2tf32(float f) {
    unsigned u;
    asm("cvt.rna.tf32.f32 %0, %1;" : "=r"(u) : "f"(f));
    return u;
}
__device__ __forceinline__ float tf32r(float f) {
    return __uint_as_float(f2tf32(f));
}
// K-REMAP CONVENTION: within each mma k8-step, fragment slot t (t=0..3)
// carries global k = kk + 2t, slot t+4 carries k = kk + 2t + 1. Valid since
// mma reduces over all 8 slots; both A and B fragments use the same map.
__device__ __forceinline__ void mma_tf32(
    float c[4], unsigned a0, unsigned a1, unsigned a2, unsigned a3,
    unsigned b0, unsigned b1)
{
    asm volatile(
        "mma.sync.aligned.m16n8k8.row.col.f32.tf32.tf32.f32 "
        "{%0,%1,%2,%3}, {%4,%5,%6,%7}, {%8,%9}, {%0,%1,%2,%3};\n"
        : "+f"(c[0]), "+f"(c[1]), "+f"(c[2]), "+f"(c[3])
        : "r"(a0), "r"(a1), "r"(a2), "r"(a3), "r"(b0), "r"(b1));
}
__device__ __forceinline__ void cp_async16(void* smem_dst, const void* gsrc) {
    unsigned s = (unsigned)__cvta_generic_to_shared(smem_dst);
    asm volatile("cp.async.cg.shared.global [%0], [%1], 16;\n" :: "r"(s), "l"(gsrc));
}
__device__ __forceinline__ void cp_commit() {
    asm volatile("cp.async.commit_group;\n");
}
template<int N>
__device__ __forceinline__ void cp_wait() {
    asm volatile("cp.async.wait_group %0;\n" :: "n"(N));
}

// Fast 2^x on the FMA/ALU pipes (no MUFU).
__device__ __forceinline__ float exp2_fast(float x) {
    float xc = fmaxf(x, -126.f);
    float fi = floorf(xc);
    float f = xc - fi;
    float p = 1.5403530e-4f;
    p = fmaf(p, f, 1.3333558e-3f);
    p = fmaf(p, f, 9.6181291e-3f);
    p = fmaf(p, f, 5.5504109e-2f);
    p = fmaf(p, f, 2.4022651e-1f);
    p = fmaf(p, f, 6.9314718e-1f);
    p = fmaf(p, f, 1.0f);
    int i = (int)fi;
    return __int_as_float((i + 127) << 23) * p;
}

// ---------------------------------------------------------------------------
// tf32 pre-round kernel (weights)
// ---------------------------------------------------------------------------
__global__ __launch_bounds__(256) void tf32_round_kernel(
    const float* __restrict__ in, float* __restrict__ out, int n4)
{
    int i = blockIdx.x * 256 + threadIdx.x;
    if (i < n4) {
        float4 v = ((const float4*)in)[i];
        float4 o;
        o.x = tf32r(v.x); o.y = tf32r(v.y); o.z = tf32r(v.z); o.w = tf32r(v.w);
        ((float4*)out)[i] = o;
    }
}

// ---------------------------------------------------------------------------
// LayerNorm (output tf32-rounded)
// ---------------------------------------------------------------------------
__device__ __forceinline__ float block_reduce_sum(float v, float* red) {
    int lane = threadIdx.x & 31, wid = threadIdx.x >> 5;
    #pragma unroll
    for (int o = 16; o > 0; o >>= 1) v += __shfl_xor_sync(0xffffffffu, v, o);
    if (lane == 0) red[wid] = v;
    __syncthreads();
    v = (lane < 8) ? red[lane] : 0.f;
    #pragma unroll
    for (int o = 4; o > 0; o >>= 1) v += __shfl_xor_sync(0xffffffffu, v, o);
    v = __shfl_sync(0xffffffffu, v, 0);
    return v;
}

__global__ __launch_bounds__(256) void ln_kernel(
    const float* __restrict__ x, const float* __restrict__ g,
    const float* __restrict__ b, float* __restrict__ out)
{
    __shared__ float red[8];
    size_t row = blockIdx.x;
    const float4* xr = (const float4*)(x + row * DIM);
    int t = threadIdx.x;
    float4 v = xr[t];
    float s = v.x + v.y + v.z + v.w;
    float mean = block_reduce_sum(s, red) * (1.f / DIM);
    __syncthreads();
    float dx0 = v.x - mean, dx1 = v.y - mean, dx2 = v.z - mean, dx3 = v.w - mean;
    float s2 = dx0*dx0 + dx1*dx1 + dx2*dx2 + dx3*dx3;
    float var = block_reduce_sum(s2, red) * (1.f / DIM);
    float rs = rsqrtf(var + EPS);
    float4 gg = ((const float4*)g)[t];
    float4 bb = ((const float4*)b)[t];
    float4 o;
    o.x = tf32r(dx0 * rs * gg.x + bb.x);
    o.y = tf32r(dx1 * rs * gg.y + bb.y);
    o.z = tf32r(dx2 * rs * gg.z + bb.z);
    o.w = tf32r(dx3 * rs * gg.w + bb.w);
    ((float4*)(out + row * DIM))[t] = o;
}

// ---------------------------------------------------------------------------
// TF32 GEMM-NT v8: 256x128x16 CTA, 512 threads, 4-stage cp.async ring,
// prefetch distance 2 issued PRE-barrier (overlaps the barrier wait),
// ONE __syncthreads per k-tile.
// Safety: prefetch target (t+2)%4 was read at t-2; passing barrier t-1
// guarantees all warps finished mma(t-2). Empty commit_groups keep group
// accounting uniform so wait_group<2> always means "group t landed".
// Mainloop body identical to R12 (v2 k-remap fragment loads, RST=24).
// ---------------------------------------------------------------------------
#define EPI_BIAS 1
#define EPI_GELU 2
#define EPI_RES  4
#define EPI_T32O 8

#define GBM 256
#define GBN 128
#define GBK 16
#define RST 24
#define A_FLOATS (GBM * RST)                  // 6144
#define B_FLOATS (GBN * RST)                  // 3072
#define STG_FLOATS (A_FLOATS + B_FLOATS)      // 9216
#define GEMM_SMEM (4 * STG_FLOATS * (int)sizeof(float))   // 147456

template<int FLAGS>
__global__ __launch_bounds__(512, 1) void gemm_tf32(
    const float* __restrict__ A, const float* __restrict__ Bw,
    const float* __restrict__ bias, const float* __restrict__ res,
    float* __restrict__ C, int M, int Nc, int K)
{
    extern __shared__ float sm[];

    int tid = threadIdx.x;
    int m0 = blockIdx.y * GBM, n0 = blockIdx.x * GBN;

    int warp = tid >> 5, lane = tid & 31;
    int wm = warp & 3, wn = warp >> 2;      // 4 m x 4 n warp grid
    int mb = wm * 64, nb = wn * 32;
    int g  = lane >> 2;
    int tg = lane & 3;

    int l_row = tid >> 2;                   // 0..127
    int l_chk = (tid & 3) << 2;

    float acc[4][4][4];
    #pragma unroll
    for (int i = 0; i < 4; i++)
        #pragma unroll
        for (int j = 0; j < 4; j++)
            #pragma unroll
            for (int c = 0; c < 4; c++) acc[i][j][c] = 0.f;

    const int T = K / GBK;

    int arow[2];
    #pragma unroll
    for (int r = 0; r < 2; r++) {
        int rr = m0 + l_row + 128 * r;
        arow[r] = rr < M ? rr : M - 1;
    }
    const float* Ap0 = A + (size_t)arow[0] * K;
    const float* Ap1 = A + (size_t)arow[1] * K;
    const float* Bp  = Bw + (size_t)(n0 + l_row) * K;

    auto load_stage = [&](int s, int k0) {
        float* As = sm + s * STG_FLOATS;
        float* Bs = As + A_FLOATS;
        cp_async16(&As[l_row * RST + l_chk], Ap0 + k0 + l_chk);
        cp_async16(&As[(l_row + 128) * RST + l_chk], Ap1 + k0 + l_chk);
        cp_async16(&Bs[l_row * RST + l_chk], Bp + k0 + l_chk);
    };

    // prologue: stages 0 and 1 (groups 0 and 1)
    load_stage(0, 0);
    cp_commit();
    load_stage(1, GBK);
    cp_commit();

    for (int t = 0; t < T; t++) {
        // prefetch t+2 (pre-barrier: overlaps the barrier wait). Empty commit
        // when out of range keeps the group count uniform.
        if (t + 2 < T) load_stage((t + 2) & 3, (t + 2) * GBK);
        cp_commit();
        cp_wait<2>();          // group t complete (t+1, t+2 may be pending)
        __syncthreads();

        const float* stage = sm + (t & 3) * STG_FLOATS;
        const unsigned* as = (const unsigned*)stage;
        const unsigned* bs = (const unsigned*)(stage + A_FLOATS);
        #pragma unroll
        for (int ks = 0; ks < 2; ks++) {
            int kk = ks * 8;
            unsigned a[4][4];
            #pragma unroll
            for (int i = 0; i < 4; i++) {
                int r0 = (mb + i * 16 + g) * RST + kk + 2 * tg;
                uint2 lo = *(const uint2*)(as + r0);
                uint2 hi = *(const uint2*)(as + r0 + 8 * RST);
                a[i][0] = lo.x; a[i][2] = lo.y;
                a[i][1] = hi.x; a[i][3] = hi.y;
            }
            #pragma unroll
            for (int j = 0; j < 4; j++) {
                int c0 = (nb + j * 8 + g) * RST + kk + 2 * tg;
                uint2 bb = *(const uint2*)(bs + c0);
                #pragma unroll
                for (int i = 0; i < 4; i++)
                    mma_tf32(acc[i][j], a[i][0], a[i][1], a[i][2], a[i][3], bb.x, bb.y);
            }
        }
    }

    #pragma unroll
    for (int i = 0; i < 4; i++) {
        #pragma unroll
        for (int j = 0; j < 4; j++) {
            int row0 = m0 + mb + i * 16 + g;
            int col  = n0 + nb + j * 8 + tg * 2;
            float bia0 = 0.f, bia1 = 0.f;
            if (FLAGS & EPI_BIAS) { bia0 = bias[col]; bia1 = bias[col + 1]; }
            #pragma unroll
            for (int half = 0; half < 2; half++) {
                int r = row0 + half * 8;
                if (r < M) {
                    float v0 = acc[i][j][half * 2 + 0] + bia0;
                    float v1 = acc[i][j][half * 2 + 1] + bia1;
                    if (FLAGS & EPI_GELU) {
                        v0 = 0.5f * v0 * (1.f + erff(v0 * 0.70710678118654752f));
                        v1 = 0.5f * v1 * (1.f + erff(v1 * 0.70710678118654752f));
                    }
                    size_t base = (size_t)r * Nc + col;
                    if (FLAGS & EPI_RES) {
                        float2 rr = *(const float2*)(res + base);
                        v0 += rr.x; v1 += rr.y;
                    }
                    if (FLAGS & EPI_T32O) { v0 = tf32r(v0); v1 = tf32r(v1); }
                    float2 o; o.x = v0; o.y = v1;
                    *(float2*)(C + base) = o;
                }
            }
        }
    }
}

// ---------------------------------------------------------------------------
// Attention v6 (unchanged from R12): register flash, k-remap, no shuffles.
// ---------------------------------------------------------------------------
#define FQ4   128
#define FC4   64
#define NCH4  10
#define QST4  72
#define KST4  72
#define VST4  68
#define A4_Q  0
#define A4_K  (A4_Q + FQ4 * QST4)               // 9216
#define A4_V  (A4_K + 2 * FC4 * KST4)           // 18432
#define ATT4_SMEM ((A4_V + 2 * FC4 * VST4) * (int)sizeof(float))  // 108544

__global__ __launch_bounds__(256, 2) void attn6_kernel(
    const float* __restrict__ qkv, float* __restrict__ out)
{
    extern __shared__ float sm[];
    float* qs = sm + A4_Q;
    float* kb = sm + A4_K;
    float* vb = sm + A4_V;

    int bh = blockIdx.y;
    int b = bh >> 4, h = bh & 15;
    int q0 = blockIdx.x * FQ4;
    int t = threadIdx.x;
    int warp = t >> 5, lane = t & 31;
    int g = lane >> 2, tg = lane & 3;
    int mb = warp * 16;

    const float* kq = qkv + (size_t)b * SEQ * (3 * DIM) + DIM + h * HDIM;
    const float* vq = qkv + (size_t)b * SEQ * (3 * DIM) + 2 * DIM + h * HDIM;

    for (int idx = t; idx < FQ4 * 16; idx += 256) {
        int r = idx >> 4, c4 = (idx & 15) << 2;
        int qr = q0 + r; if (qr >= SEQ) qr = SEQ - 1;
        float4 v = *(const float4*)(qkv + (size_t)(b * SEQ + qr) * (3 * DIM) + h * HDIM + c4);
        *(float4*)(qs + r * QST4 + c4) = v;
    }

    float m0 = -1e30f, m1 = -1e30f, l0 = 0.f, l1 = 0.f;
    float oacc[8][4];
    #pragma unroll
    for (int j = 0; j < 8; j++)
        #pragma unroll
        for (int c = 0; c < 4; c++) oacc[j][c] = 0.f;

    for (int idx = t; idx < FC4 * 16; idx += 256) {
        int r = idx >> 4, c4 = (idx & 15) << 2;
        int kr = r; if (kr >= SEQ) kr = SEQ - 1;
        cp_async16(&kb[r * KST4 + c4], kq + (size_t)kr * (3 * DIM) + c4);
        cp_async16(&vb[r * VST4 + c4], vq + (size_t)kr * (3 * DIM) + c4);
    }
    cp_commit();

    for (int c = 0; c < NCH4; c++) {
        int buf = c & 1;
        const float* kbuf = kb + buf * FC4 * KST4;
        const float* vbuf = vb + buf * FC4 * VST4;
        if (c + 1 < NCH4) {
            float* kn = kb + (buf ^ 1) * FC4 * KST4;
            float* vn = vb + (buf ^ 1) * FC4 * VST4;
            for (int idx = t; idx < FC4 * 16; idx += 256) {
                int r = idx >> 4, c4 = (idx & 15) << 2;
                int kr = (c + 1) * FC4 + r; if (kr >= SEQ) kr = SEQ - 1;
                cp_async16(&kn[r * KST4 + c4], kq + (size_t)kr * (3 * DIM) + c4);
                cp_async16(&vn[r * VST4 + c4], vq + (size_t)kr * (3 * DIM) + c4);
            }
            cp_commit();
            cp_wait<1>();
        } else {
            cp_wait<0>();
        }
        __syncthreads();

        // ---- S = Q @ K^T (v2 frag loads, k-remap) ----
        float p[8][4];
        #pragma unroll
        for (int j = 0; j < 8; j++)
            #pragma unroll
            for (int e = 0; e < 4; e++) p[j][e] = 0.f;

        const unsigned* ku = (const unsigned*)kbuf;
        const unsigned* qu = (const unsigned*)qs;
        #pragma unroll
        for (int k8 = 0; k8 < 8; k8++) {
            int kk = k8 * 8;
            int q0i = (mb + g) * QST4 + kk + 2 * tg;
            uint2 qa = *(const uint2*)(qu + q0i);
            uint2 qb = *(const uint2*)(qu + q0i + 8 * QST4);
            unsigned a0 = qa.x, a2 = qa.y, a1 = qb.x, a3 = qb.y;
            #pragma unroll
            for (int j = 0; j < 8; j++) {
                uint2 kv = *(const uint2*)(ku + (8 * j + g) * KST4 + kk + 2 * tg);
                mma_tf32(p[j], a0, a1, a2, a3, kv.x, kv.y);
            }
        }

        #pragma unroll
        for (int j = 0; j < 8; j++) {
            int gcol = c * FC4 + 8 * j + 2 * tg;
            bool ok0 = (gcol < SEQ), ok1 = (gcol + 1 < SEQ);
            p[j][0] = ok0 ? p[j][0] * SCL2 : -1e30f;
            p[j][1] = ok1 ? p[j][1] * SCL2 : -1e30f;
            p[j][2] = ok0 ? p[j][2] * SCL2 : -1e30f;
            p[j][3] = ok1 ? p[j][3] * SCL2 : -1e30f;
        }

        float cm0 = -1e30f, cm1 = -1e30f;
        #pragma unroll
        for (int j = 0; j < 8; j++) {
            cm0 = fmaxf(cm0, fmaxf(p[j][0], p[j][1]));
            cm1 = fmaxf(cm1, fmaxf(p[j][2], p[j][3]));
        }
        cm0 = fmaxf(cm0, __shfl_xor_sync(0xffffffffu, cm0, 1, 4));
        cm0 = fmaxf(cm0, __shfl_xor_sync(0xffffffffu, cm0, 2, 4));
        cm1 = fmaxf(cm1, __shfl_xor_sync(0xffffffffu, cm1, 1, 4));
        cm1 = fmaxf(cm1, __shfl_xor_sync(0xffffffffu, cm1, 2, 4));

        float mn0 = fmaxf(m0, cm0), mn1 = fmaxf(m1, cm1);
        float al0 = exp2_fast(m0 - mn0), al1 = exp2_fast(m1 - mn1);
        float s0 = 0.f, s1 = 0.f;
        #pragma unroll
        for (int j = 0; j < 8; j++) {
            p[j][0] = exp2_fast(p[j][0] - mn0); s0 += p[j][0];
            p[j][1] = exp2_fast(p[j][1] - mn0); s0 += p[j][1];
            p[j][2] = exp2_fast(p[j][2] - mn1); s1 += p[j][2];
            p[j][3] = exp2_fast(p[j][3] - mn1); s1 += p[j][3];
        }
        s0 += __shfl_xor_sync(0xffffffffu, s0, 1, 4);
        s0 += __shfl_xor_sync(0xffffffffu, s0, 2, 4);
        s1 += __shfl_xor_sync(0xffffffffu, s1, 1, 4);
        s1 += __shfl_xor_sync(0xffffffffu, s1, 2, 4);
        l0 = l0 * al0 + s0;  m0 = mn0;
        l1 = l1 * al1 + s1;  m1 = mn1;

        #pragma unroll
        for (int j = 0; j < 8; j++) {
            oacc[j][0] *= al0; oacc[j][1] *= al0;
            oacc[j][2] *= al1; oacc[j][3] *= al1;
        }

        // ---- O += P @ V : k-remap makes S-output fragment == A-fragment.
        const unsigned* vu = (const unsigned*)vbuf;
        #pragma unroll
        for (int jj = 0; jj < 8; jj++) {
            unsigned A0 = f2tf32(p[jj][0]);
            unsigned A1 = f2tf32(p[jj][2]);
            unsigned A2 = f2tf32(p[jj][1]);
            unsigned A3 = f2tf32(p[jj][3]);
            int vr0 = (8 * jj + 2 * tg) * VST4;
            int vr1 = vr0 + VST4;
            #pragma unroll
            for (int j2 = 0; j2 < 8; j2++) {
                unsigned b0 = vu[vr0 + 8 * j2 + g];
                unsigned b1 = vu[vr1 + 8 * j2 + g];
                mma_tf32(oacc[j2], A0, A1, A2, A3, b0, b1);
            }
        }
        __syncthreads();
    }

    {
        float li0 = 1.f / l0, li1 = 1.f / l1;
        #pragma unroll
        for (int j2 = 0; j2 < 8; j2++) {
            int col = h * HDIM + 8 * j2 + 2 * tg;
            int r0 = q0 + mb + g, r1 = r0 + 8;
            if (r0 < SEQ) {
                float2 o; o.x = tf32r(oacc[j2][0] * li0); o.y = tf32r(oacc[j2][1] * li0);
                *(float2*)(out + (size_t)(b * SEQ + r0) * DIM + col) = o;
            }
            if (r1 < SEQ) {
                float2 o; o.x = tf32r(oacc[j2][2] * li1); o.y = tf32r(oacc[j2][3] * li1);
                *(float2*)(out + (size_t)(b * SEQ + r1) * DIM + col) = o;
            }
        }
    }
}

// ---------------------------------------------------------------------------
// Launch
// ---------------------------------------------------------------------------
extern "C" void kernel_launch(void* const* d_in, const int* in_sizes, int n_in,
                              void* d_out, int out_size)
{
    const float* x      = (const float*)d_in[0];
    const float* w_qkv  = (const float*)d_in[1];
    const float* b_qkv  = (const float*)d_in[2];
    const float* w_proj = (const float*)d_in[3];
    const float* b_proj = (const float*)d_in[4];
    const float* ln1_g  = (const float*)d_in[5];
    const float* ln1_b  = (const float*)d_in[6];
    const float* ln2_g  = (const float*)d_in[7];
    const float* ln2_b  = (const float*)d_in[8];
    const float* w_fc1  = (const float*)d_in[9];
    const float* b_fc1  = (const float*)d_in[10];
    const float* w_fc2  = (const float*)d_in[11];
    const float* b_fc2  = (const float*)d_in[12];
    float* out = (float*)d_out;

    float *p_xn, *p_qkv, *p_y, *p_x1, *p_h, *p_wq, *p_wp, *p_w1, *p_w2;
    cudaGetSymbolAddress((void**)&p_xn,  g_xn);
    cudaGetSymbolAddress((void**)&p_qkv, g_qkv);
    cudaGetSymbolAddress((void**)&p_y,   g_y);
    cudaGetSymbolAddress((void**)&p_x1,  g_x1);
    cudaGetSymbolAddress((void**)&p_h,   g_h);
    cudaGetSymbolAddress((void**)&p_wq,  g_wq);
    cudaGetSymbolAddress((void**)&p_wp,  g_wp);
    cudaGetSymbolAddress((void**)&p_w1,  g_w1);
    cudaGetSymbolAddress((void**)&p_w2,  g_w2);

    cudaFuncSetAttribute(attn6_kernel,
        cudaFuncAttributeMaxDynamicSharedMemorySize, ATT4_SMEM);
    cudaFuncSetAttribute(gemm_tf32<EPI_BIAS | EPI_T32O>,
        cudaFuncAttributeMaxDynamicSharedMemorySize, GEMM_SMEM);
    cudaFuncSetAttribute(gemm_tf32<EPI_BIAS | EPI_RES>,
        cudaFuncAttributeMaxDynamicSharedMemorySize, GEMM_SMEM);
    cudaFuncSetAttribute(gemm_tf32<EPI_BIAS | EPI_GELU | EPI_T32O>,
        cudaFuncAttributeMaxDynamicSharedMemorySize, GEMM_SMEM);

    const int MB = (TOK + GBM - 1) / GBM;   // 37

    tf32_round_kernel<<<(3 * DIM * DIM / 4 + 255) / 256, 256>>>(w_qkv, p_wq, 3 * DIM * DIM / 4);
    tf32_round_kernel<<<(DIM * DIM / 4 + 255) / 256, 256>>>(w_proj, p_wp, DIM * DIM / 4);
    tf32_round_kernel<<<(HIDDEN * DIM / 4 + 255) / 256, 256>>>(w_fc1, p_w1, HIDDEN * DIM / 4);
    tf32_round_kernel<<<(DIM * HIDDEN / 4 + 255) / 256, 256>>>(w_fc2, p_w2, DIM * HIDDEN / 4);

    ln_kernel<<<TOK, 256>>>(x, ln1_g, ln1_b, p_xn);
    gemm_tf32<EPI_BIAS | EPI_T32O><<<dim3(3 * DIM / GBN, MB), 512, GEMM_SMEM>>>(
        p_xn, p_wq, b_qkv, nullptr, p_qkv, TOK, 3 * DIM, DIM);
    attn6_kernel<<<dim3((SEQ + FQ4 - 1) / FQ4, BATCH * HEADS), 256, ATT4_SMEM>>>(
        p_qkv, p_y);
    gemm_tf32<EPI_BIAS | EPI_RES><<<dim3(DIM / GBN, MB), 512, GEMM_SMEM>>>(
        p_y, p_wp, b_proj, x, p_x1, TOK, DIM, DIM);
    ln_kernel<<<TOK, 256>>>(p_x1, ln2_g, ln2_b, p_xn);
    gemm_tf32<EPI_BIAS | EPI_GELU | EPI_T32O><<<dim3(HIDDEN / GBN, MB), 512, GEMM_SMEM>>>(
        p_xn, p_w1, b_fc1, nullptr, p_h, TOK, HIDDEN, DIM);
    gemm_tf32<EPI_BIAS | EPI_RES><<<dim3(DIM / GBN, MB), 512, GEMM_SMEM>>>(
        p_h, p_w2, b_fc2, p_x1, out, TOK, DIM, HIDDEN);
}

// round 15
// speedup vs baseline: 1.5410x; 1.0514x over previous
#include <cuda_runtime.h>
#include <cuda_bf16.h>
#include <math.h>

// ---------------------------------------------------------------------------
// Problem constants
// ---------------------------------------------------------------------------
#define BATCH   16
#define SEQ     577
#define TOK     (BATCH * SEQ)        // 9232
#define DIM     1024
#define HEADS   16
#define HDIM    64
#define HIDDEN  4096
#define EPS     1e-5f
#define SCALE   0.125f
#define SCL2    0.18033688011112042f   // SCALE * log2(e)

// ---------------------------------------------------------------------------
// Scratch
// ---------------------------------------------------------------------------
__device__ float g_xn [TOK * DIM];
__device__ float g_qkv[TOK * 3 * DIM];
__device__ float g_y  [TOK * DIM];
__device__ float g_x1 [TOK * DIM];
__device__ float g_h  [TOK * HIDDEN];
__device__ float g_wq [3 * DIM * DIM];
__device__ float g_wp [DIM * DIM];
__device__ float g_w1 [HIDDEN * DIM];
__device__ float g_w2 [DIM * HIDDEN];

// ---------------------------------------------------------------------------
// Common helpers
// ---------------------------------------------------------------------------
__device__ __forceinline__ unsigned f2tf32(float f) {
    unsigned u;
    asm("cvt.rna.tf32.f32 %0, %1;" : "=r"(u) : "f"(f));
    return u;
}
__device__ __forceinline__ float tf32r(float f) {
    return __uint_as_float(f2tf32(f));
}
// K-REMAP CONVENTION: within each mma k8-step, fragment slot t (t=0..3)
// carries global k = kk + 2t, slot t+4 carries k = kk + 2t + 1. Valid since
// mma reduces over all 8 slots; both A and B fragments use the same map.
__device__ __forceinline__ void mma_tf32(
    float c[4], unsigned a0, unsigned a1, unsigned a2, unsigned a3,
    unsigned b0, unsigned b1)
{
    asm volatile(
        "mma.sync.aligned.m16n8k8.row.col.f32.tf32.tf32.f32 "
        "{%0,%1,%2,%3}, {%4,%5,%6,%7}, {%8,%9}, {%0,%1,%2,%3};\n"
        : "+f"(c[0]), "+f"(c[1]), "+f"(c[2]), "+f"(c[3])
        : "r"(a0), "r"(a1), "r"(a2), "r"(a3), "r"(b0), "r"(b1));
}
__device__ __forceinline__ void cp_async16(void* smem_dst, const void* gsrc) {
    unsigned s = (unsigned)__cvta_generic_to_shared(smem_dst);
    asm volatile("cp.async.cg.shared.global [%0], [%1], 16;\n" :: "r"(s), "l"(gsrc));
}
__device__ __forceinline__ void cp_commit() {
    asm volatile("cp.async.commit_group;\n");
}
template<int N>
__device__ __forceinline__ void cp_wait() {
    asm volatile("cp.async.wait_group %0;\n" :: "n"(N));
}

// Fast 2^x on the FMA/ALU pipes (no MUFU).
__device__ __forceinline__ float exp2_fast(float x) {
    float xc = fmaxf(x, -126.f);
    float fi = floorf(xc);
    float f = xc - fi;
    float p = 1.5403530e-4f;
    p = fmaf(p, f, 1.3333558e-3f);
    p = fmaf(p, f, 9.6181291e-3f);
    p = fmaf(p, f, 5.5504109e-2f);
    p = fmaf(p, f, 2.4022651e-1f);
    p = fmaf(p, f, 6.9314718e-1f);
    p = fmaf(p, f, 1.0f);
    int i = (int)fi;
    return __int_as_float((i + 127) << 23) * p;
}

// ---------------------------------------------------------------------------
// tf32 pre-round kernel (weights)
// ---------------------------------------------------------------------------
__global__ __launch_bounds__(256) void tf32_round_kernel(
    const float* __restrict__ in, float* __restrict__ out, int n4)
{
    int i = blockIdx.x * 256 + threadIdx.x;
    if (i < n4) {
        float4 v = ((const float4*)in)[i];
        float4 o;
        o.x = tf32r(v.x); o.y = tf32r(v.y); o.z = tf32r(v.z); o.w = tf32r(v.w);
        ((float4*)out)[i] = o;
    }
}

// ---------------------------------------------------------------------------
// LayerNorm (output tf32-rounded)
// ---------------------------------------------------------------------------
__device__ __forceinline__ float block_reduce_sum(float v, float* red) {
    int lane = threadIdx.x & 31, wid = threadIdx.x >> 5;
    #pragma unroll
    for (int o = 16; o > 0; o >>= 1) v += __shfl_xor_sync(0xffffffffu, v, o);
    if (lane == 0) red[wid] = v;
    __syncthreads();
    v = (lane < 8) ? red[lane] : 0.f;
    #pragma unroll
    for (int o = 4; o > 0; o >>= 1) v += __shfl_xor_sync(0xffffffffu, v, o);
    v = __shfl_sync(0xffffffffu, v, 0);
    return v;
}

__global__ __launch_bounds__(256) void ln_kernel(
    const float* __restrict__ x, const float* __restrict__ g,
    const float* __restrict__ b, float* __restrict__ out)
{
    __shared__ float red[8];
    size_t row = blockIdx.x;
    const float4* xr = (const float4*)(x + row * DIM);
    int t = threadIdx.x;
    float4 v = xr[t];
    float s = v.x + v.y + v.z + v.w;
    float mean = block_reduce_sum(s, red) * (1.f / DIM);
    __syncthreads();
    float dx0 = v.x - mean, dx1 = v.y - mean, dx2 = v.z - mean, dx3 = v.w - mean;
    float s2 = dx0*dx0 + dx1*dx1 + dx2*dx2 + dx3*dx3;
    float var = block_reduce_sum(s2, red) * (1.f / DIM);
    float rs = rsqrtf(var + EPS);
    float4 gg = ((const float4*)g)[t];
    float4 bb = ((const float4*)b)[t];
    float4 o;
    o.x = tf32r(dx0 * rs * gg.x + bb.x);
    o.y = tf32r(dx1 * rs * gg.y + bb.y);
    o.z = tf32r(dx2 * rs * gg.z + bb.z);
    o.w = tf32r(dx3 * rs * gg.w + bb.w);
    ((float4*)(out + row * DIM))[t] = o;
}

// ---------------------------------------------------------------------------
// TF32 GEMM-NT v9: 256x128x32 CTA, 512 threads, 3-stage cp.async ring,
// distance-1 prefetch issued PRE-barrier, ONE __syncthreads per k-tile.
// Safety: prefetch target (t+1)%3 was last read at t-2; barrier t-1 fenced
// mma(t-2), and stragglers can only be reading (t-1)%3 != (t+1)%3.
// RST=40: v2 pair-bank coeff 20 mod 16 = 4 -> conflict-free per 16-lane phase.
// ---------------------------------------------------------------------------
#define EPI_BIAS 1
#define EPI_GELU 2
#define EPI_RES  4
#define EPI_T32O 8

#define GBM 256
#define GBN 128
#define GBK 32
#define RST 40
#define A_FLOATS (GBM * RST)                  // 10240
#define B_FLOATS (GBN * RST)                  // 5120
#define STG_FLOATS (A_FLOATS + B_FLOATS)      // 15360
#define GEMM_SMEM (3 * STG_FLOATS * (int)sizeof(float))   // 184320

template<int FLAGS>
__global__ __launch_bounds__(512, 1) void gemm_tf32(
    const float* __restrict__ A, const float* __restrict__ Bw,
    const float* __restrict__ bias, const float* __restrict__ res,
    float* __restrict__ C, int M, int Nc, int K)
{
    extern __shared__ float sm[];

    int tid = threadIdx.x;
    int m0 = blockIdx.y * GBM, n0 = blockIdx.x * GBN;

    int warp = tid >> 5, lane = tid & 31;
    int wm = warp & 3, wn = warp >> 2;      // 4 m x 4 n warp grid
    int mb = wm * 64, nb = wn * 32;
    int g  = lane >> 2;
    int tg = lane & 3;

    float acc[4][4][4];
    #pragma unroll
    for (int i = 0; i < 4; i++)
        #pragma unroll
        for (int j = 0; j < 4; j++)
            #pragma unroll
            for (int c = 0; c < 4; c++) acc[i][j][c] = 0.f;

    const int T = K / GBK;

    // loader chunks: A = 256 rows x 8 float4-chunks = 2048 -> 4/thread;
    //                B = 128 rows x 8               = 1024 -> 2/thread.
    int a_lr[4], a_lc[4]; const float* a_ptr[4];
    #pragma unroll
    for (int c = 0; c < 4; c++) {
        int id = tid + c * 512;
        a_lr[c] = id >> 3;
        a_lc[c] = (id & 7) << 2;
        int gr = m0 + a_lr[c]; if (gr >= M) gr = M - 1;
        a_ptr[c] = A + (size_t)gr * K + a_lc[c];
    }
    int b_lr[2], b_lc[2]; const float* b_ptr[2];
    #pragma unroll
    for (int c = 0; c < 2; c++) {
        int id = tid + c * 512;
        b_lr[c] = id >> 3;
        b_lc[c] = (id & 7) << 2;
        b_ptr[c] = Bw + (size_t)(n0 + b_lr[c]) * K + b_lc[c];
    }

    auto load_stage = [&](int s, int k0) {
        float* As = sm + s * STG_FLOATS;
        float* Bs = As + A_FLOATS;
        #pragma unroll
        for (int c = 0; c < 4; c++)
            cp_async16(&As[a_lr[c] * RST + a_lc[c]], a_ptr[c] + k0);
        #pragma unroll
        for (int c = 0; c < 2; c++)
            cp_async16(&Bs[b_lr[c] * RST + b_lc[c]], b_ptr[c] + k0);
    };

    // prologue: stage 0 (group 0)
    load_stage(0, 0);
    cp_commit();

    int stg = 0;
    for (int t = 0; t < T; t++) {
        // distance-1 prefetch pre-barrier (overlaps barrier wait)
        if (t + 1 < T) {
            int ns = stg + 1; if (ns == 3) ns = 0;
            load_stage(ns, (t + 1) * GBK);
        }
        cp_commit();
        cp_wait<1>();          // group t complete
        __syncthreads();

        const float* stage = sm + stg * STG_FLOATS;
        const unsigned* as = (const unsigned*)stage;
        const unsigned* bs = (const unsigned*)(stage + A_FLOATS);
        #pragma unroll
        for (int ks = 0; ks < 4; ks++) {
            int kk = ks * 8;
            unsigned a[4][4];
            #pragma unroll
            for (int i = 0; i < 4; i++) {
                int r0 = (mb + i * 16 + g) * RST + kk + 2 * tg;
                uint2 lo = *(const uint2*)(as + r0);
                uint2 hi = *(const uint2*)(as + r0 + 8 * RST);
                a[i][0] = lo.x; a[i][2] = lo.y;
                a[i][1] = hi.x; a[i][3] = hi.y;
            }
            #pragma unroll
            for (int j = 0; j < 4; j++) {
                int c0 = (nb + j * 8 + g) * RST + kk + 2 * tg;
                uint2 bb = *(const uint2*)(bs + c0);
                #pragma unroll
                for (int i = 0; i < 4; i++)
                    mma_tf32(acc[i][j], a[i][0], a[i][1], a[i][2], a[i][3], bb.x, bb.y);
            }
        }
        stg = stg + 1; if (stg == 3) stg = 0;
    }

    #pragma unroll
    for (int i = 0; i < 4; i++) {
        #pragma unroll
        for (int j = 0; j < 4; j++) {
            int row0 = m0 + mb + i * 16 + g;
            int col  = n0 + nb + j * 8 + tg * 2;
            float bia0 = 0.f, bia1 = 0.f;
            if (FLAGS & EPI_BIAS) { bia0 = bias[col]; bia1 = bias[col + 1]; }
            #pragma unroll
            for (int half = 0; half < 2; half++) {
                int r = row0 + half * 8;
                if (r < M) {
                    float v0 = acc[i][j][half * 2 + 0] + bia0;
                    float v1 = acc[i][j][half * 2 + 1] + bia1;
                    if (FLAGS & EPI_GELU) {
                        v0 = 0.5f * v0 * (1.f + erff(v0 * 0.70710678118654752f));
                        v1 = 0.5f * v1 * (1.f + erff(v1 * 0.70710678118654752f));
                    }
                    size_t base = (size_t)r * Nc + col;
                    if (FLAGS & EPI_RES) {
                        float2 rr = *(const float2*)(res + base);
                        v0 += rr.x; v1 += rr.y;
                    }
                    if (FLAGS & EPI_T32O) { v0 = tf32r(v0); v1 = tf32r(v1); }
                    float2 o; o.x = v0; o.y = v1;
                    *(float2*)(C + base) = o;
                }
            }
        }
    }
}

// ---------------------------------------------------------------------------
// Attention v6 (unchanged from R12): register flash, k-remap, no shuffles.
// ---------------------------------------------------------------------------
#define FQ4   128
#define FC4   64
#define NCH4  10
#define QST4  72
#define KST4  72
#define VST4  68
#define A4_Q  0
#define A4_K  (A4_Q + FQ4 * QST4)               // 9216
#define A4_V  (A4_K + 2 * FC4 * KST4)           // 18432
#define ATT4_SMEM ((A4_V + 2 * FC4 * VST4) * (int)sizeof(float))  // 108544

__global__ __launch_bounds__(256, 2) void attn6_kernel(
    const float* __restrict__ qkv, float* __restrict__ out)
{
    extern __shared__ float sm[];
    float* qs = sm + A4_Q;
    float* kb = sm + A4_K;
    float* vb = sm + A4_V;

    int bh = blockIdx.y;
    int b = bh >> 4, h = bh & 15;
    int q0 = blockIdx.x * FQ4;
    int t = threadIdx.x;
    int warp = t >> 5, lane = t & 31;
    int g = lane >> 2, tg = lane & 3;
    int mb = warp * 16;

    const float* kq = qkv + (size_t)b * SEQ * (3 * DIM) + DIM + h * HDIM;
    const float* vq = qkv + (size_t)b * SEQ * (3 * DIM) + 2 * DIM + h * HDIM;

    for (int idx = t; idx < FQ4 * 16; idx += 256) {
        int r = idx >> 4, c4 = (idx & 15) << 2;
        int qr = q0 + r; if (qr >= SEQ) qr = SEQ - 1;
        float4 v = *(const float4*)(qkv + (size_t)(b * SEQ + qr) * (3 * DIM) + h * HDIM + c4);
        *(float4*)(qs + r * QST4 + c4) = v;
    }

    float m0 = -1e30f, m1 = -1e30f, l0 = 0.f, l1 = 0.f;
    float oacc[8][4];
    #pragma unroll
    for (int j = 0; j < 8; j++)
        #pragma unroll
        for (int c = 0; c < 4; c++) oacc[j][c] = 0.f;

    for (int idx = t; idx < FC4 * 16; idx += 256) {
        int r = idx >> 4, c4 = (idx & 15) << 2;
        int kr = r; if (kr >= SEQ) kr = SEQ - 1;
        cp_async16(&kb[r * KST4 + c4], kq + (size_t)kr * (3 * DIM) + c4);
        cp_async16(&vb[r * VST4 + c4], vq + (size_t)kr * (3 * DIM) + c4);
    }
    cp_commit();

    for (int c = 0; c < NCH4; c++) {
        int buf = c & 1;
        const float* kbuf = kb + buf * FC4 * KST4;
        const float* vbuf = vb + buf * FC4 * VST4;
        if (c + 1 < NCH4) {
            float* kn = kb + (buf ^ 1) * FC4 * KST4;
            float* vn = vb + (buf ^ 1) * FC4 * VST4;
            for (int idx = t; idx < FC4 * 16; idx += 256) {
                int r = idx >> 4, c4 = (idx & 15) << 2;
                int kr = (c + 1) * FC4 + r; if (kr >= SEQ) kr = SEQ - 1;
                cp_async16(&kn[r * KST4 + c4], kq + (size_t)kr * (3 * DIM) + c4);
                cp_async16(&vn[r * VST4 + c4], vq + (size_t)kr * (3 * DIM) + c4);
            }
            cp_commit();
            cp_wait<1>();
        } else {
            cp_wait<0>();
        }
        __syncthreads();

        // ---- S = Q @ K^T (v2 frag loads, k-remap) ----
        float p[8][4];
        #pragma unroll
        for (int j = 0; j < 8; j++)
            #pragma unroll
            for (int e = 0; e < 4; e++) p[j][e] = 0.f;

        const unsigned* ku = (const unsigned*)kbuf;
        const unsigned* qu = (const unsigned*)qs;
        #pragma unroll
        for (int k8 = 0; k8 < 8; k8++) {
            int kk = k8 * 8;
            int q0i = (mb + g) * QST4 + kk + 2 * tg;
            uint2 qa = *(const uint2*)(qu + q0i);
            uint2 qb = *(const uint2*)(qu + q0i + 8 * QST4);
            unsigned a0 = qa.x, a2 = qa.y, a1 = qb.x, a3 = qb.y;
            #pragma unroll
            for (int j = 0; j < 8; j++) {
                uint2 kv = *(const uint2*)(ku + (8 * j + g) * KST4 + kk + 2 * tg);
                mma_tf32(p[j], a0, a1, a2, a3, kv.x, kv.y);
            }
        }

        #pragma unroll
        for (int j = 0; j < 8; j++) {
            int gcol = c * FC4 + 8 * j + 2 * tg;
            bool ok0 = (gcol < SEQ), ok1 = (gcol + 1 < SEQ);
            p[j][0] = ok0 ? p[j][0] * SCL2 : -1e30f;
            p[j][1] = ok1 ? p[j][1] * SCL2 : -1e30f;
            p[j][2] = ok0 ? p[j][2] * SCL2 : -1e30f;
            p[j][3] = ok1 ? p[j][3] * SCL2 : -1e30f;
        }

        float cm0 = -1e30f, cm1 = -1e30f;
        #pragma unroll
        for (int j = 0; j < 8; j++) {
            cm0 = fmaxf(cm0, fmaxf(p[j][0], p[j][1]));
            cm1 = fmaxf(cm1, fmaxf(p[j][2], p[j][3]));
        }
        cm0 = fmaxf(cm0, __shfl_xor_sync(0xffffffffu, cm0, 1, 4));
        cm0 = fmaxf(cm0, __shfl_xor_sync(0xffffffffu, cm0, 2, 4));
        cm1 = fmaxf(cm1, __shfl_xor_sync(0xffffffffu, cm1, 1, 4));
        cm1 = fmaxf(cm1, __shfl_xor_sync(0xffffffffu, cm1, 2, 4));

        float mn0 = fmaxf(m0, cm0), mn1 = fmaxf(m1, cm1);
        float al0 = exp2_fast(m0 - mn0), al1 = exp2_fast(m1 - mn1);
        float s0 = 0.f, s1 = 0.f;
        #pragma unroll
        for (int j = 0; j < 8; j++) {
            p[j][0] = exp2_fast(p[j][0] - mn0); s0 += p[j][0];
            p[j][1] = exp2_fast(p[j][1] - mn0); s0 += p[j][1];
            p[j][2] = exp2_fast(p[j][2] - mn1); s1 += p[j][2];
            p[j][3] = exp2_fast(p[j][3] - mn1); s1 += p[j][3];
        }
        s0 += __shfl_xor_sync(0xffffffffu, s0, 1, 4);
        s0 += __shfl_xor_sync(0xffffffffu, s0, 2, 4);
        s1 += __shfl_xor_sync(0xffffffffu, s1, 1, 4);
        s1 += __shfl_xor_sync(0xffffffffu, s1, 2, 4);
        l0 = l0 * al0 + s0;  m0 = mn0;
        l1 = l1 * al1 + s1;  m1 = mn1;

        #pragma unroll
        for (int j = 0; j < 8; j++) {
            oacc[j][0] *= al0; oacc[j][1] *= al0;
            oacc[j][2] *= al1; oacc[j][3] *= al1;
        }

        // ---- O += P @ V : k-remap makes S-output fragment == A-fragment.
        const unsigned* vu = (const unsigned*)vbuf;
        #pragma unroll
        for (int jj = 0; jj < 8; jj++) {
            unsigned A0 = f2tf32(p[jj][0]);
            unsigned A1 = f2tf32(p[jj][2]);
            unsigned A2 = f2tf32(p[jj][1]);
            unsigned A3 = f2tf32(p[jj][3]);
            int vr0 = (8 * jj + 2 * tg) * VST4;
            int vr1 = vr0 + VST4;
            #pragma unroll
            for (int j2 = 0; j2 < 8; j2++) {
                unsigned b0 = vu[vr0 + 8 * j2 + g];
                unsigned b1 = vu[vr1 + 8 * j2 + g];
                mma_tf32(oacc[j2], A0, A1, A2, A3, b0, b1);
            }
        }
        __syncthreads();
    }

    {
        float li0 = 1.f / l0, li1 = 1.f / l1;
        #pragma unroll
        for (int j2 = 0; j2 < 8; j2++) {
            int col = h * HDIM + 8 * j2 + 2 * tg;
            int r0 = q0 + mb + g, r1 = r0 + 8;
            if (r0 < SEQ) {
                float2 o; o.x = tf32r(oacc[j2][0] * li0); o.y = tf32r(oacc[j2][1] * li0);
                *(float2*)(out + (size_t)(b * SEQ + r0) * DIM + col) = o;
            }
            if (r1 < SEQ) {
                float2 o; o.x = tf32r(oacc[j2][2] * li1); o.y = tf32r(oacc[j2][3] * li1);
                *(float2*)(out + (size_t)(b * SEQ + r1) * DIM + col) = o;
            }
        }
    }
}

// ---------------------------------------------------------------------------
// Launch
// ---------------------------------------------------------------------------
extern "C" void kernel_launch(void* const* d_in, const int* in_sizes, int n_in,
                              void* d_out, int out_size)
{
    const float* x      = (const float*)d_in[0];
    const float* w_qkv  = (const float*)d_in[1];
    const float* b_qkv  = (const float*)d_in[2];
    const float* w_proj = (const float*)d_in[3];
    const float* b_proj = (const float*)d_in[4];
    const float* ln1_g  = (const float*)d_in[5];
    const float* ln1_b  = (const float*)d_in[6];
    const float* ln2_g  = (const float*)d_in[7];
    const float* ln2_b  = (const float*)d_in[8];
    const float* w_fc1  = (const float*)d_in[9];
    const float* b_fc1  = (const float*)d_in[10];
    const float* w_fc2  = (const float*)d_in[11];
    const float* b_fc2  = (const float*)d_in[12];
    float* out = (float*)d_out;

    float *p_xn, *p_qkv, *p_y, *p_x1, *p_h, *p_wq, *p_wp, *p_w1, *p_w2;
    cudaGetSymbolAddress((void**)&p_xn,  g_xn);
    cudaGetSymbolAddress((void**)&p_qkv, g_qkv);
    cudaGetSymbolAddress((void**)&p_y,   g_y);
    cudaGetSymbolAddress((void**)&p_x1,  g_x1);
    cudaGetSymbolAddress((void**)&p_h,   g_h);
    cudaGetSymbolAddress((void**)&p_wq,  g_wq);
    cudaGetSymbolAddress((void**)&p_wp,  g_wp);
    cudaGetSymbolAddress((void**)&p_w1,  g_w1);
    cudaGetSymbolAddress((void**)&p_w2,  g_w2);

    cudaFuncSetAttribute(attn6_kernel,
        cudaFuncAttributeMaxDynamicSharedMemorySize, ATT4_SMEM);
    cudaFuncSetAttribute(gemm_tf32<EPI_BIAS | EPI_T32O>,
        cudaFuncAttributeMaxDynamicSharedMemorySize, GEMM_SMEM);
    cudaFuncSetAttribute(gemm_tf32<EPI_BIAS | EPI_RES>,
        cudaFuncAttributeMaxDynamicSharedMemorySize, GEMM_SMEM);
    cudaFuncSetAttribute(gemm_tf32<EPI_BIAS | EPI_GELU | EPI_T32O>,
        cudaFuncAttributeMaxDynamicSharedMemorySize, GEMM_SMEM);

    const int MB = (TOK + GBM - 1) / GBM;   // 37

    tf32_round_kernel<<<(3 * DIM * DIM / 4 + 255) / 256, 256>>>(w_qkv, p_wq, 3 * DIM * DIM / 4);
    tf32_round_kernel<<<(DIM * DIM / 4 + 255) / 256, 256>>>(w_proj, p_wp, DIM * DIM / 4);
    tf32_round_kernel<<<(HIDDEN * DIM / 4 + 255) / 256, 256>>>(w_fc1, p_w1, HIDDEN * DIM / 4);
    tf32_round_kernel<<<(DIM * HIDDEN / 4 + 255) / 256, 256>>>(w_fc2, p_w2, DIM * HIDDEN / 4);

    ln_kernel<<<TOK, 256>>>(x, ln1_g, ln1_b, p_xn);
    gemm_tf32<EPI_BIAS | EPI_T32O><<<dim3(3 * DIM / GBN, MB), 512, GEMM_SMEM>>>(
        p_xn, p_wq, b_qkv, nullptr, p_qkv, TOK, 3 * DIM, DIM);
    attn6_kernel<<<dim3((SEQ + FQ4 - 1) / FQ4, BATCH * HEADS), 256, ATT4_SMEM>>>(
        p_qkv, p_y);
    gemm_tf32<EPI_BIAS | EPI_RES><<<dim3(DIM / GBN, MB), 512, GEMM_SMEM>>>(
        p_y, p_wp, b_proj, x, p_x1, TOK, DIM, DIM);
    ln_kernel<<<TOK, 256>>>(p_x1, ln2_g, ln2_b, p_xn);
    gemm_tf32<EPI_BIAS | EPI_GELU | EPI_T32O><<<dim3(HIDDEN / GBN, MB), 512, GEMM_SMEM>>>(
        p_xn, p_w1, b_fc1, nullptr, p_h, TOK, HIDDEN, DIM);
    gemm_tf32<EPI_BIAS | EPI_RES><<<dim3(DIM / GBN, MB), 512, GEMM_SMEM>>>(
        p_h, p_w2, b_fc2, p_x1, out, TOK, DIM, HIDDEN);
}